// round 1
// baseline (speedup 1.0000x reference)
#include <cuda_runtime.h>

// Problem constants (fixed by the reference)
#define Bn 32
#define Nn 1024
#define Fn 128   // F_IN
#define Dn 128   // DIM*NUM_HEAD

// Scratch (static __device__ — no allocation allowed)
__device__ float g_XsumP[Bn][8][Fn];   // per-slice partial column sums of X
__device__ float g_u[Bn][Fn];          // u[b] = Wq @ ksum[b]
__device__ float g_c[Bn];              // c[b] = bq . ksum[b]
__device__ float g_agg[Bn][Nn];        // masked pre-softmax logits
__device__ float g_yP[Bn][8][Fn];      // partial weighted X sums
__device__ float g_wsum[Bn];           // sum of w = mask*attn

// K1: column-sum partials of X. grid (B,8) x 256 thr. Each block: 128 rows.
__global__ void k1_xsum(const float* __restrict__ X) {
    int b = blockIdx.x, j = blockIdx.y;
    int t = threadIdx.x;
    int f4 = t & 31, g = t >> 5;               // 32 float4 cols, 8 row-groups
    const float4* Xb = (const float4*)(X + (size_t)b * Nn * Fn);
    float4 acc = make_float4(0.f, 0.f, 0.f, 0.f);
    int rowBase = j * 128 + g * 16;
    #pragma unroll
    for (int r = 0; r < 16; r++) {
        float4 x = Xb[(size_t)(rowBase + r) * 32 + f4];
        acc.x += x.x; acc.y += x.y; acc.z += x.z; acc.w += x.w;
    }
    __shared__ float4 part[8][32];
    part[g][f4] = acc;
    __syncthreads();
    if (t < 32) {
        float4 s = part[0][t];
        #pragma unroll
        for (int gg = 1; gg < 8; gg++) {
            float4 p = part[gg][t];
            s.x += p.x; s.y += p.y; s.z += p.z; s.w += p.w;
        }
        ((float4*)g_XsumP[b][j])[t] = s;
    }
}

// K2: ksum -> u, c. grid B x 128 thr.
__global__ void k2_uc(const float* __restrict__ Wq, const float* __restrict__ bq,
                      const float* __restrict__ Wk, const float* __restrict__ bk) {
    int b = blockIdx.x, t = threadIdx.x;
    __shared__ float Xs[Fn];
    __shared__ float ks[Dn];
    __shared__ float red[128];
    float s = 0.f;
    #pragma unroll
    for (int j = 0; j < 8; j++) s += g_XsumP[b][j][t];
    Xs[t] = s;
    __syncthreads();
    float acc = (float)Nn * bk[t];
    #pragma unroll 8
    for (int f = 0; f < Fn; f++) acc += Xs[f] * Wk[f * Dn + t];
    ks[t] = acc;
    __syncthreads();
    float uacc = 0.f;
    #pragma unroll 8
    for (int d = 0; d < Dn; d++) uacc += Wq[t * Dn + d] * ks[d];
    g_u[b][t] = uacc;
    red[t] = bq[t] * ks[t];
    __syncthreads();
    for (int off = 64; off > 0; off >>= 1) {
        if (t < off) red[t] += red[t + off];
        __syncthreads();
    }
    if (t == 0) g_c[b] = red[0];
}

// K3: agg[b,n] = mask ? dk*(X[b,n].u[b] + c[b]) : -1e9. Warp per row.
// grid 4096 x 256 thr (8 warps = 8 rows per block).
__global__ void k3_agg(const float* __restrict__ X, const float* __restrict__ mask) {
    int t = threadIdx.x, w = t >> 5, lane = t & 31;
    int b = blockIdx.x >> 7;
    int n = ((blockIdx.x & 127) << 3) + w;
    __shared__ float us[Fn];
    if (t < 128) us[t] = g_u[b][t];
    __syncthreads();
    const float4* xr = (const float4*)(X + ((size_t)b * Nn + n) * Fn);
    float4 x = xr[lane];
    float d = x.x * us[lane * 4] + x.y * us[lane * 4 + 1]
            + x.z * us[lane * 4 + 2] + x.w * us[lane * 4 + 3];
    #pragma unroll
    for (int off = 16; off > 0; off >>= 1)
        d += __shfl_down_sync(0xffffffffu, d, off);
    if (lane == 0) {
        float m = mask[b * Nn + n];
        // dk = 128^{-0.5}
        g_agg[b][n] = (m != 0.0f) ? 0.08838834764831843f * (d + g_c[b]) : -1e9f;
    }
}

// K4: per-batch softmax (redundant per j-slice), write attn, accumulate y partials.
// grid (B,8) x 256 thr.
__global__ void k4_softmax_y(const float* __restrict__ X, const float* __restrict__ mask,
                             float* __restrict__ attn_out) {
    int b = blockIdx.x, j = blockIdx.y, t = threadIdx.x;
    __shared__ float e[Nn];
    __shared__ float red[256];
    __shared__ float wrow[128];
    __shared__ float4 part[8][32];

    float a0 = g_agg[b][t];
    float a1 = g_agg[b][t + 256];
    float a2 = g_agg[b][t + 512];
    float a3 = g_agg[b][t + 768];
    float lm = fmaxf(fmaxf(a0, a1), fmaxf(a2, a3));
    red[t] = lm;
    __syncthreads();
    for (int off = 128; off > 0; off >>= 1) {
        if (t < off) red[t] = fmaxf(red[t], red[t + off]);
        __syncthreads();
    }
    float M = red[0];
    __syncthreads();

    float e0 = expf(a0 - M), e1 = expf(a1 - M), e2 = expf(a2 - M), e3 = expf(a3 - M);
    e[t] = e0; e[t + 256] = e1; e[t + 512] = e2; e[t + 768] = e3;
    red[t] = e0 + e1 + e2 + e3;
    __syncthreads();
    for (int off = 128; off > 0; off >>= 1) {
        if (t < off) red[t] += red[t + off];
        __syncthreads();
    }
    float invZ = 1.0f / red[0];
    __syncthreads();

    // attn output + w for this block's 128 rows
    if (t < 128) {
        int n = j * 128 + t;
        float en = e[n];
        attn_out[b * Nn + n] = en * invZ;
        wrow[t] = mask[b * Nn + n] * en * invZ;
    }
    // wsum (only j==0 block writes)
    float ws = 0.f;
    if (j == 0) {
        ws = mask[b * Nn + t] * e0 + mask[b * Nn + t + 256] * e1
           + mask[b * Nn + t + 512] * e2 + mask[b * Nn + t + 768] * e3;
    }
    __syncthreads();
    if (j == 0) {
        red[t] = ws;
        __syncthreads();
        for (int off = 128; off > 0; off >>= 1) {
            if (t < off) red[t] += red[t + off];
            __syncthreads();
        }
        if (t == 0) g_wsum[b] = red[0] * invZ;
    }

    // y partial: y[b,f] += sum_n wrow[n] * X[b,n,f] over this block's 128 rows
    int f4 = t & 31, g = t >> 5;
    const float4* Xb = (const float4*)(X + (size_t)b * Nn * Fn);
    float4 acc = make_float4(0.f, 0.f, 0.f, 0.f);
    int rowBase = j * 128 + g * 16;
    #pragma unroll
    for (int r = 0; r < 16; r++) {
        float wn = wrow[g * 16 + r];
        float4 x = Xb[(size_t)(rowBase + r) * 32 + f4];
        acc.x += wn * x.x; acc.y += wn * x.y; acc.z += wn * x.z; acc.w += wn * x.w;
    }
    part[g][f4] = acc;
    __syncthreads();
    if (t < 32) {
        float4 s = part[0][t];
        #pragma unroll
        for (int gg = 1; gg < 8; gg++) {
            float4 p = part[gg][t];
            s.x += p.x; s.y += p.y; s.z += p.z; s.w += p.w;
        }
        ((float4*)g_yP[b][j])[t] = s;
    }
}

// K5: context[b,d] = (sum_j yP).Wv[:,d] + wsum*bv[d]. grid B x 128 thr.
__global__ void k5_ctx(const float* __restrict__ Wv, const float* __restrict__ bv,
                       float* __restrict__ ctx_out) {
    int b = blockIdx.x, t = threadIdx.x;
    __shared__ float y[Fn];
    float s = 0.f;
    #pragma unroll
    for (int j = 0; j < 8; j++) s += g_yP[b][j][t];
    y[t] = s;
    __syncthreads();
    float acc = g_wsum[b] * bv[t];
    #pragma unroll 8
    for (int f = 0; f < Fn; f++) acc += y[f] * Wv[f * Dn + t];
    ctx_out[b * Dn + t] = acc;
}

extern "C" void kernel_launch(void* const* d_in, const int* in_sizes, int n_in,
                              void* d_out, int out_size) {
    const float* X    = (const float*)d_in[0];  // atom_query [B,N,F]
    const float* mask = (const float*)d_in[1];  // [B,N,1]
    const float* Wq   = (const float*)d_in[2];
    const float* bq   = (const float*)d_in[3];
    const float* Wk   = (const float*)d_in[4];
    const float* bk   = (const float*)d_in[5];
    const float* Wv   = (const float*)d_in[6];
    const float* bv   = (const float*)d_in[7];
    float* out  = (float*)d_out;
    float* attn = out;              // [B,N,1] -> B*N floats
    float* ctx  = out + Bn * Nn;    // [B,D]   -> B*D floats

    k1_xsum<<<dim3(Bn, 8), 256>>>(X);
    k2_uc<<<Bn, 128>>>(Wq, bq, Wk, bk);
    k3_agg<<<4096, 256>>>(X, mask);
    k4_softmax_y<<<dim3(Bn, 8), 256>>>(X, mask, attn);
    k5_ctx<<<Bn, 128>>>(Wv, bv, ctx);
}

// round 2
// speedup vs baseline: 1.0136x; 1.0136x over previous
#include <cuda_runtime.h>
#include <math_constants.h>

// Problem constants (fixed by the reference)
#define Bn 32
#define Nn 1024
#define Fn 128
#define Dn 128
#define SL 16                      // slices per batch
#define RPB (Nn / SL)              // 64 rows per block

// Scratch (static __device__ — no allocation allowed)
__device__ float g_XsumP[Bn][SL][Fn];  // per-slice partial column sums of X
__device__ float g_u[Bn][Fn];          // u[b] = Wq @ ksum[b]
__device__ float g_c[Bn];              // c[b] = bq . ksum[b]
__device__ float g_agg[Bn][Nn];        // masked pre-softmax logits
__device__ float g_M[Bn][SL];          // per-slice online-softmax max
__device__ float g_S[Bn][SL];          // per-slice online-softmax sum
__device__ float g_acc[Bn][SL][Fn];    // per-slice Sum e*X partial

// ---------------------------------------------------------------------------
// K1: column-sum partials of X. grid (B, SL) x 256 thr. Each block: 64 rows.
__global__ void k1_xsum(const float* __restrict__ X) {
    int b = blockIdx.x, s = blockIdx.y, t = threadIdx.x;
    int f4 = t & 31, g = t >> 5;                 // 32 float4 cols, 8 row-groups
    const float4* Xb = (const float4*)(X + (size_t)b * Nn * Fn);
    float4 acc = make_float4(0.f, 0.f, 0.f, 0.f);
    int rowBase = s * RPB + g * 8;
    #pragma unroll
    for (int r = 0; r < 8; r++) {
        float4 x = Xb[(size_t)(rowBase + r) * 32 + f4];
        acc.x += x.x; acc.y += x.y; acc.z += x.z; acc.w += x.w;
    }
    __shared__ float4 part[8][32];
    part[g][f4] = acc;
    __syncthreads();
    if (t < 32) {
        float4 sum = part[0][t];
        #pragma unroll
        for (int gg = 1; gg < 8; gg++) {
            float4 p = part[gg][t];
            sum.x += p.x; sum.y += p.y; sum.z += p.z; sum.w += p.w;
        }
        ((float4*)g_XsumP[b][s])[t] = sum;
    }
}

// ---------------------------------------------------------------------------
// K2: ksum -> u, c. grid B x 128 thr.
__global__ void k2_uc(const float* __restrict__ Wq, const float* __restrict__ bq,
                      const float* __restrict__ Wk, const float* __restrict__ bk) {
    int b = blockIdx.x, t = threadIdx.x;
    __shared__ float Xs[Fn];
    __shared__ float ks[Dn];
    __shared__ float red[128];
    float s = 0.f;
    #pragma unroll
    for (int j = 0; j < SL; j++) s += g_XsumP[b][j][t];
    Xs[t] = s;
    __syncthreads();
    float acc = (float)Nn * bk[t];
    #pragma unroll 8
    for (int f = 0; f < Fn; f++) acc += Xs[f] * Wk[f * Dn + t];
    ks[t] = acc;
    __syncthreads();
    float uacc = 0.f;
    #pragma unroll 8
    for (int d = 0; d < Dn; d++) uacc += Wq[t * Dn + d] * ks[d];
    g_u[b][t] = uacc;
    red[t] = bq[t] * ks[t];
    __syncthreads();
    for (int off = 64; off > 0; off >>= 1) {
        if (t < off) red[t] += red[t + off];
        __syncthreads();
    }
    if (t == 0) g_c[b] = red[0];
}

// ---------------------------------------------------------------------------
// K3: fused agg + online-softmax weighted accumulation of X.
// grid (B, SL) x 256 thr (8 warps, 8 rows/warp). Each row's float4 is loaded
// ONCE into registers, used for both the q.u dot and the e-weighted acc.
__global__ void k3_aggacc(const float* __restrict__ X, const float* __restrict__ mask) {
    int b = blockIdx.x, s = blockIdx.y, t = threadIdx.x;
    int w = t >> 5, lane = t & 31;
    __shared__ float us[Fn];
    if (t < 128) us[t] = g_u[b][t];
    __syncthreads();
    float c = g_c[b];
    float4 uv = ((float4*)us)[lane];

    int row0 = s * RPB + w * 8;
    const float4* Xr = (const float4*)(X + ((size_t)b * Nn + row0) * Fn);
    float4 x[8];
    #pragma unroll
    for (int r = 0; r < 8; r++) x[r] = Xr[(size_t)r * 32 + lane];
    float mv = (lane < 8) ? mask[b * Nn + row0 + lane] : 0.f;

    float M = -3.0e38f, Ssum = 0.f;
    float4 acc = make_float4(0.f, 0.f, 0.f, 0.f);
    #pragma unroll
    for (int r = 0; r < 8; r++) {
        float d = x[r].x * uv.x + x[r].y * uv.y + x[r].z * uv.z + x[r].w * uv.w;
        #pragma unroll
        for (int off = 16; off > 0; off >>= 1)
            d += __shfl_xor_sync(0xffffffffu, d, off);
        float mval = __shfl_sync(0xffffffffu, mv, r);
        float a = (mval != 0.f) ? 0.08838834764831843f * (d + c) : -1e9f;
        if (lane == 0) g_agg[b][row0 + r] = a;
        float newM = fmaxf(M, a);
        float sc = __expf(M - newM);
        float ev = __expf(a - newM);
        Ssum = Ssum * sc + ev;
        acc.x = acc.x * sc + ev * x[r].x;
        acc.y = acc.y * sc + ev * x[r].y;
        acc.z = acc.z * sc + ev * x[r].z;
        acc.w = acc.w * sc + ev * x[r].w;
        M = newM;
    }

    // combine 8 warp partials -> block partial
    __shared__ float Mw[8], Sw[8];
    __shared__ float4 accw[8][32];
    if (lane == 0) { Mw[w] = M; Sw[w] = Ssum; }
    accw[w][lane] = acc;
    __syncthreads();
    if (t < 32) {
        float bM = Mw[0];
        #pragma unroll
        for (int j = 1; j < 8; j++) bM = fmaxf(bM, Mw[j]);
        float Sb = 0.f;
        float4 ya = make_float4(0.f, 0.f, 0.f, 0.f);
        #pragma unroll
        for (int j = 0; j < 8; j++) {
            float f = __expf(Mw[j] - bM);
            Sb += f * Sw[j];
            float4 p = accw[j][t];
            ya.x += f * p.x; ya.y += f * p.y; ya.z += f * p.z; ya.w += f * p.w;
        }
        ((float4*)g_acc[b][s])[t] = ya;
        if (t == 0) { g_M[b][s] = bM; g_S[b][s] = Sb; }
    }
}

// ---------------------------------------------------------------------------
// K4: merge slice partials -> Z, M, y; write context and attn. grid B x 128.
__global__ void k4_final(const float* __restrict__ Wv, const float* __restrict__ bv,
                         float* __restrict__ attn, float* __restrict__ ctx) {
    int b = blockIdx.x, t = threadIdx.x;
    __shared__ float Msh[SL], Ssh[SL], ys[Fn];
    if (t < SL) { Msh[t] = g_M[b][t]; Ssh[t] = g_S[b][t]; }
    __syncthreads();
    float bM = -3.0e38f;
    #pragma unroll
    for (int j = 0; j < SL; j++) bM = fmaxf(bM, Msh[j]);
    float Z = 0.f, y = 0.f;
    #pragma unroll
    for (int j = 0; j < SL; j++) {
        float f = __expf(Msh[j] - bM);
        Z += f * Ssh[j];
        y += f * g_acc[b][j][t];
    }
    float invZ = 1.0f / Z;
    ys[t] = y * invZ;
    __syncthreads();
    // context[b,t] = (y/Z) . Wv[:,t] + 1.0*bv[t]   (wsum == 1 exactly in fp32)
    float a = bv[t];
    #pragma unroll 8
    for (int f = 0; f < Fn; f++) a += ys[f] * Wv[f * Dn + t];
    ctx[b * Dn + t] = a;
    // attn output
    #pragma unroll
    for (int i = 0; i < 8; i++) {
        int n = t + i * 128;
        attn[b * Nn + n] = __expf(g_agg[b][n] - bM) * invZ;
    }
}

// ---------------------------------------------------------------------------
extern "C" void kernel_launch(void* const* d_in, const int* in_sizes, int n_in,
                              void* d_out, int out_size) {
    const float* X    = (const float*)d_in[0];  // atom_query [B,N,F]
    const float* mask = (const float*)d_in[1];  // [B,N,1]
    const float* Wq   = (const float*)d_in[2];
    const float* bq   = (const float*)d_in[3];
    const float* Wk   = (const float*)d_in[4];
    const float* bk   = (const float*)d_in[5];
    const float* Wv   = (const float*)d_in[6];
    const float* bv   = (const float*)d_in[7];
    float* out  = (float*)d_out;
    float* attn = out;              // [B,N,1]
    float* ctx  = out + Bn * Nn;    // [B,D]

    k1_xsum<<<dim3(Bn, SL), 256>>>(X);
    k2_uc<<<Bn, 128>>>(Wq, bq, Wk, bk);
    k3_aggacc<<<dim3(Bn, SL), 256>>>(X, mask);
    k4_final<<<Bn, 128>>>(Wv, bv, attn, ctx);
}

// round 3
// speedup vs baseline: 1.0667x; 1.0523x over previous
#include <cuda_runtime.h>

// Problem constants (fixed by the reference)
#define Bn 32
#define Nn 1024
#define Fn 128
#define Dn 128
#define SL 16                       // slices per batch
#define RPB (Nn / SL)               // 64 rows per slice-block
#define NBLK (Bn * SL)              // 512 blocks

// Scratch (static __device__ — no allocation allowed)
__device__ float g_XsumP[Bn][SL][Fn];
__device__ float g_u[Bn][Fn];
__device__ float g_c[Bn];
__device__ float g_agg[Bn][Nn];
__device__ float g_M[Bn][SL];
__device__ float g_S[Bn][SL];
__device__ float g_acc[Bn][SL][Fn];

// Grid barrier state (self-resetting across launches: cnt returns to 0,
// gen strictly increases; equality-compare makes wraparound harmless)
__device__ unsigned g_cnt = 0;
__device__ volatile unsigned g_gen = 0;

__device__ __forceinline__ void gsync() {
    __syncthreads();
    if (threadIdx.x == 0) {
        unsigned my = g_gen;
        __threadfence();                       // publish this block's writes
        if (atomicAdd(&g_cnt, 1u) == NBLK - 1u) {
            g_cnt = 0;
            __threadfence();                   // cnt reset visible before release
            g_gen = my + 1u;
        } else {
            while (g_gen == my) __nanosleep(32);
        }
        __threadfence();                       // acquire
    }
    __syncthreads();
}

__global__ __launch_bounds__(256, 4)
void ga_fused(const float* __restrict__ X, const float* __restrict__ mask,
              const float* __restrict__ Wq, const float* __restrict__ bq,
              const float* __restrict__ Wk, const float* __restrict__ bk,
              const float* __restrict__ Wv, const float* __restrict__ bv,
              float* __restrict__ attn, float* __restrict__ ctx) {
    int bid = blockIdx.x, t = threadIdx.x;
    int b = bid >> 4, s = bid & 15;
    int w = t >> 5, lane = t & 31;

    __shared__ float4 shA[8][32];                 // phase A partials
    __shared__ float shXs[Fn], shKs[Dn], shRed[128];   // phase B
    __shared__ float shU[Fn], shMw[8], shSw[8];   // phase C
    __shared__ float4 shAcc[8][32];               // phase C
    __shared__ float shM[SL], shS[SL], shY[Fn];   // phase D

    // ---------------- Phase A: column-sum partials of X (all 512 blocks) ----
    {
        const float4* Xb = (const float4*)(X + (size_t)b * Nn * Fn);
        float4 acc = make_float4(0.f, 0.f, 0.f, 0.f);
        int rowBase = s * RPB + w * 8;
        #pragma unroll
        for (int r = 0; r < 8; r++) {
            float4 x = Xb[(size_t)(rowBase + r) * 32 + lane];
            acc.x += x.x; acc.y += x.y; acc.z += x.z; acc.w += x.w;
        }
        shA[w][lane] = acc;
        __syncthreads();
        if (t < 32) {
            float4 sum = shA[0][t];
            #pragma unroll
            for (int g = 1; g < 8; g++) {
                float4 p = shA[g][t];
                sum.x += p.x; sum.y += p.y; sum.z += p.z; sum.w += p.w;
            }
            ((float4*)g_XsumP[b][s])[t] = sum;
        }
    }
    gsync();

    // ---------------- Phase B: ksum -> u, c (blocks 0..31) ------------------
    if (bid < Bn) {
        int bb = bid;
        if (t < 128) {
            float sm = 0.f;
            #pragma unroll
            for (int j = 0; j < SL; j++) sm += g_XsumP[bb][j][t];
            shXs[t] = sm;
        }
        __syncthreads();
        if (t < 128) {
            float acc = (float)Nn * bk[t];
            #pragma unroll 8
            for (int f = 0; f < Fn; f++) acc += shXs[f] * Wk[f * Dn + t];
            shKs[t] = acc;
        }
        __syncthreads();
        if (t < 128) {
            float uacc = 0.f;
            #pragma unroll 8
            for (int d = 0; d < Dn; d++) uacc += Wq[t * Dn + d] * shKs[d];
            g_u[bb][t] = uacc;
            shRed[t] = bq[t] * shKs[t];
        }
        __syncthreads();
        for (int off = 64; off > 0; off >>= 1) {
            if (t < off) shRed[t] += shRed[t + off];
            __syncthreads();
        }
        if (t == 0) g_c[bb] = shRed[0];
    }
    gsync();

    // ---------------- Phase C: fused agg + online-softmax acc (all blocks) --
    {
        if (t < 128) shU[t] = g_u[b][t];
        __syncthreads();
        float c = g_c[b];
        float4 uv = ((float4*)shU)[lane];

        int row0 = s * RPB + w * 8;
        const float4* Xr = (const float4*)(X + ((size_t)b * Nn + row0) * Fn);
        float4 x[8];
        #pragma unroll
        for (int r = 0; r < 8; r++) x[r] = Xr[(size_t)r * 32 + lane];
        float mv = (lane < 8) ? mask[b * Nn + row0 + lane] : 0.f;

        float M = -3.0e38f, Ssum = 0.f;
        float4 acc = make_float4(0.f, 0.f, 0.f, 0.f);
        #pragma unroll
        for (int r = 0; r < 8; r++) {
            float d = x[r].x * uv.x + x[r].y * uv.y + x[r].z * uv.z + x[r].w * uv.w;
            #pragma unroll
            for (int off = 16; off > 0; off >>= 1)
                d += __shfl_xor_sync(0xffffffffu, d, off);
            float mval = __shfl_sync(0xffffffffu, mv, r);
            float a = (mval != 0.f) ? 0.08838834764831843f * (d + c) : -1e9f;
            if (lane == 0) g_agg[b][row0 + r] = a;
            float newM = fmaxf(M, a);
            float sc = __expf(M - newM);
            float ev = __expf(a - newM);
            Ssum = Ssum * sc + ev;
            acc.x = acc.x * sc + ev * x[r].x;
            acc.y = acc.y * sc + ev * x[r].y;
            acc.z = acc.z * sc + ev * x[r].z;
            acc.w = acc.w * sc + ev * x[r].w;
            M = newM;
        }

        if (lane == 0) { shMw[w] = M; shSw[w] = Ssum; }
        shAcc[w][lane] = acc;
        __syncthreads();
        if (t < 32) {
            float bM = shMw[0];
            #pragma unroll
            for (int j = 1; j < 8; j++) bM = fmaxf(bM, shMw[j]);
            float Sb = 0.f;
            float4 ya = make_float4(0.f, 0.f, 0.f, 0.f);
            #pragma unroll
            for (int j = 0; j < 8; j++) {
                float f = __expf(shMw[j] - bM);
                Sb += f * shSw[j];
                float4 p = shAcc[j][t];
                ya.x += f * p.x; ya.y += f * p.y; ya.z += f * p.z; ya.w += f * p.w;
            }
            ((float4*)g_acc[b][s])[t] = ya;
            if (t == 0) { g_M[b][s] = bM; g_S[b][s] = Sb; }
        }
    }
    gsync();

    // ---------------- Phase D: merge + attn + context (blocks 0..31) --------
    if (bid < Bn) {
        int bb = bid;
        if (t < SL) { shM[t] = g_M[bb][t]; shS[t] = g_S[bb][t]; }
        __syncthreads();
        float bM = -3.0e38f;
        #pragma unroll
        for (int j = 0; j < SL; j++) bM = fmaxf(bM, shM[j]);
        float Z = 0.f;
        #pragma unroll
        for (int j = 0; j < SL; j++) Z += __expf(shM[j] - bM) * shS[j];
        float invZ = 1.0f / Z;

        if (t < 128) {
            float y = 0.f;
            #pragma unroll
            for (int j = 0; j < SL; j++)
                y += __expf(shM[j] - bM) * g_acc[bb][j][t];
            shY[t] = y * invZ;
        }
        // attn: 4 rows per thread, independent of shY
        #pragma unroll
        for (int i = 0; i < 4; i++) {
            int n = t + i * 256;
            attn[bb * Nn + n] = __expf(g_agg[bb][n] - bM) * invZ;
        }
        __syncthreads();
        if (t < 128) {
            // context[bb,t] = shY . Wv[:,t] + bv[t]   (wsum == 1 exactly)
            float a0 = 0.f, a1 = 0.f, a2 = 0.f, a3 = 0.f;
            #pragma unroll 8
            for (int f = 0; f < Fn; f += 4) {
                a0 += shY[f]     * Wv[(f)     * Dn + t];
                a1 += shY[f + 1] * Wv[(f + 1) * Dn + t];
                a2 += shY[f + 2] * Wv[(f + 2) * Dn + t];
                a3 += shY[f + 3] * Wv[(f + 3) * Dn + t];
            }
            ctx[bb * Dn + t] = bv[t] + ((a0 + a1) + (a2 + a3));
        }
    }
}

extern "C" void kernel_launch(void* const* d_in, const int* in_sizes, int n_in,
                              void* d_out, int out_size) {
    const float* X    = (const float*)d_in[0];
    const float* mask = (const float*)d_in[1];
    const float* Wq   = (const float*)d_in[2];
    const float* bq   = (const float*)d_in[3];
    const float* Wk   = (const float*)d_in[4];
    const float* bk   = (const float*)d_in[5];
    const float* Wv   = (const float*)d_in[6];
    const float* bv   = (const float*)d_in[7];
    float* out  = (float*)d_out;
    float* attn = out;              // [B,N,1]
    float* ctx  = out + Bn * Nn;    // [B,D]

    ga_fused<<<NBLK, 256>>>(X, mask, Wq, bq, Wk, bk, Wv, bv, attn, ctx);
}